// round 1
// baseline (speedup 1.0000x reference)
#include <cuda_runtime.h>
#include <cuda_bf16.h>

// QuantumLayer analytic collapse:
//   out[b,i] = prod_{c in S_i} cos(x[b,c]),
//   S_i = { c <= i : ((i-c) & (L-1)) == 0 }   (L = number of RZ/CNOT layers)
// Derivation: RZ layers are unit-modulus diagonal phases -> do not affect
// probabilities; CNOT chains are GF(2)-linear basis permutations; Z_i after
// L layers pulls back to a parity of initial-wire Z's; product measure
// factorizes expectation into a product of cos(x_c). q_weights is unused.

__global__ void quantum_layer_kernel(const float* __restrict__ x,
                                     float* __restrict__ out,
                                     int total, int n, int Lm1) {
    int t = blockIdx.x * blockDim.x + threadIdx.x;
    if (t >= total) return;
    int b = t / n;
    int i = t - b * n;
    const float* row = x + b * n;
    float p = 1.0f;
    #pragma unroll 1
    for (int c = i; c >= 0; --c) {
        if (((i - c) & Lm1) == 0) {
            p *= cosf(__ldg(row + c));
        }
    }
    out[t] = p;
}

extern "C" void kernel_launch(void* const* d_in, const int* in_sizes, int n_in,
                              void* d_out, int out_size) {
    const float* x = (const float*)d_in[0];
    // q_weights = d_in[1] : mathematically irrelevant (phases cancel in |.|^2)
    const int n = 10;                       // wires (q_weights.shape[1])
    const int L = in_sizes[1] / n;          // layers (q_weights.shape[0]) = 2
    const int total = out_size;             // B * n

    int threads = 256;
    int blocks = (total + threads - 1) / threads;
    quantum_layer_kernel<<<blocks, threads>>>(x, (float*)d_out, total, n, L - 1);
}